// round 15
// baseline (speedup 1.0000x reference)
#include <cuda_runtime.h>
#include <cstdint>

// GNN critic encoder, fully fused: one CTA per batch row.
// R14: 8 warps/CTA (warp = (head, 16-token half)) for 2x occupancy.
//      tf32 mma layer GEMM (3-term) + aggregation (2-term), direct-LDG weights,
//      named pair barriers, no cp.async ring.

#define XSROW 132      // xs token-row stride: 132 % 32 == 4 -> frag reads conflict-free
#define PST   36       // pbuf row stride: 4*i+j banks -> A-frag reads conflict-free

__device__ __forceinline__ float elu1(float v) { return v > 0.f ? v : expm1f(v); }

// tf32 split: hi = top 10 mantissa bits (valid tf32), lo = exact residual
__device__ __forceinline__ void split_tf32(float v, unsigned& hi, unsigned& lo) {
    unsigned u = __float_as_uint(v) & 0xFFFFE000u;
    hi = u;
    lo = __float_as_uint(v - __uint_as_float(u));
}
__device__ __forceinline__ unsigned hi_tf32(float v) {
    return __float_as_uint(v) & 0xFFFFE000u;
}

__device__ __forceinline__ void mma_tf32(float c[4],
                                         unsigned a0, unsigned a1, unsigned a2, unsigned a3,
                                         unsigned b0, unsigned b1) {
    asm volatile(
        "mma.sync.aligned.m16n8k8.row.col.f32.tf32.tf32.f32 "
        "{%0,%1,%2,%3}, {%4,%5,%6,%7}, {%8,%9}, {%0,%1,%2,%3};"
        : "+f"(c[0]), "+f"(c[1]), "+f"(c[2]), "+f"(c[3])
        : "r"(a0), "r"(a1), "r"(a2), "r"(a3), "r"(b0), "r"(b1));
}

__device__ __forceinline__ void pair_bar(int head) {
    asm volatile("bar.sync %0, 64;" :: "r"(head + 1) : "memory");
}

// Token embedding: 4 tokens per warp -> xs token-major rows t0..t0+3.
template<int D>
__device__ __forceinline__ void embed_tokens(const float* __restrict__ obs_tok,
                                             const float* __restrict__ W,
                                             const float* __restrict__ bias,
                                             float* __restrict__ xs,
                                             int t0, int lane)
{
    float bb[4];
#pragma unroll
    for (int c = 0; c < 4; c++) bb[c] = __ldg(&bias[lane + 32 * c]);
    float acc[4][4];
#pragma unroll
    for (int r = 0; r < 4; r++)
#pragma unroll
        for (int c = 0; c < 4; c++) acc[r][c] = bb[c];
#pragma unroll 4
    for (int d = 0; d < D; d++) {
        float wv[4];
#pragma unroll
        for (int c = 0; c < 4; c++) wv[c] = __ldg(&W[d * 128 + lane + 32 * c]);
#pragma unroll
        for (int r = 0; r < 4; r++) {
            float xv = obs_tok[r * D + d];
#pragma unroll
            for (int c = 0; c < 4; c++) acc[r][c] += xv * wv[c];
        }
    }
#pragma unroll
    for (int r = 0; r < 4; r++)
#pragma unroll
        for (int c = 0; c < 4; c++)
            xs[(t0 + r) * XSROW + lane + 32 * c] = acc[r][c];
}

__global__ __launch_bounds__(256, 4)
void gnn_critic_kernel(const float* __restrict__ gobs,
                       const float* __restrict__ Wv, const float* __restrict__ bv,
                       const float* __restrict__ Wp, const float* __restrict__ bp,
                       const float* __restrict__ w0g, const float* __restrict__ as0,
                       const float* __restrict__ ad0,
                       const float* __restrict__ w1g, const float* __restrict__ as1,
                       const float* __restrict__ ad1,
                       float* __restrict__ out)
{
    __shared__ float xs[32 * XSROW];                  // activations / h (head bands alias)
    __shared__ __align__(16) float pbuf[4][32][PST];  // per-head unnormalized attn p
    __shared__ float as_sh[128];                      // [head*32 + token]
    __shared__ float ad_sh[128];
    __shared__ float inv_sh[128];                     // per (head, query) 1/sum
    __shared__ float alive[32];
    __shared__ float inv_cnt_sh;

    float* obs = &pbuf[0][0][0];                      // 1056 <= 4608; dead before softmax L0

    const int tid  = threadIdx.x;
    const int lane = tid & 31;
    const int warp = tid >> 5;                        // 0..7
    const int head = warp & 3;
    const int mt   = warp >> 2;                       // token half: rows mt*16..mt*16+15
    const int b    = blockIdx.x;
    const int g    = lane >> 2;                       // mma group row
    const int tig  = lane & 3;                        // thread-in-group

    // ---- load obs row ----
    const float* rowp = gobs + (long)b * 1056;
    for (int i = tid; i < 1056; i += 256) obs[i] = __ldg(&rowp[i]);
    __syncthreads();

    // ---- alive mask + all-dead fix + pool count ----
    if (warp == 0) {
        float v = (obs[1024 + lane] >= 0.5f) ? 1.0f : 0.0f;
        float s = v;
#pragma unroll
        for (int o = 16; o; o >>= 1) s += __shfl_xor_sync(0xffffffffu, s, o);
        float vv = (s < 0.5f) ? 1.0f : v;
        alive[lane] = vv;
        if (lane == 0) {
            float cnt = (s < 0.5f) ? 32.0f : s;
            inv_cnt_sh = 1.0f / fmaxf(cnt, 1.0f);
        }
    }

    // ---- token embedding: warps 0-3 veh (4 tok, D=40), 4-7 ped (4 tok, D=24) ----
    if (warp < 4)
        embed_tokens<40>(obs + warp * 4 * 40, Wv, bv, xs, warp * 4, lane);
    else
        embed_tokens<24>(obs + 640 + (warp - 4) * 4 * 24, Wp, bp, xs, 16 + (warp - 4) * 4, lane);
    __syncthreads();          // xs + alive ready; obs (pbuf) dead

    for (int L = 0; L < 2; L++) {
        const float* w    = (L ? w1g : w0g) + head * 32;     // this head's column band
        const float* asrc = L ? as1 : as0;
        const float* adst = L ? ad1 : ad0;

        // ---- GEMM: h[mt half] = x @ w via tf32 mma, 3-term. 16 rows per warp. ----
        float C[4][4];
#pragma unroll
        for (int nt = 0; nt < 4; nt++)
#pragma unroll
            for (int r = 0; r < 4; r++) C[nt][r] = 0.f;

#pragma unroll 2
        for (int kb = 0; kb < 16; kb++) {
            // A fragments from xs (own 16 rows)
            unsigned ah[4], al[4];
            const int r0 = (mt * 16 + g) * XSROW + kb * 8 + tig;
            split_tf32(xs[r0],                 ah[0], al[0]);
            split_tf32(xs[r0 + 8 * XSROW],     ah[1], al[1]);
            split_tf32(xs[r0 + 4],             ah[2], al[2]);
            split_tf32(xs[r0 + 8 * XSROW + 4], ah[3], al[3]);
            // B fragments straight from global (L2-resident weights)
            const float* wk = w + (kb * 8 + tig) * 128;
#pragma unroll
            for (int nt = 0; nt < 4; nt++) {
                float b0f = __ldg(&wk[nt * 8 + g]);
                float b1f = __ldg(&wk[4 * 128 + nt * 8 + g]);
                unsigned bh0, bl0, bh1, bl1;
                split_tf32(b0f, bh0, bl0);
                split_tf32(b1f, bh1, bl1);
                mma_tf32(C[nt], ah[0], ah[1], ah[2], ah[3], bh0, bh1);
                mma_tf32(C[nt], ah[0], ah[1], ah[2], ah[3], bl0, bl1);
                mma_tf32(C[nt], al[0], al[1], al[2], al[3], bh0, bh1);
            }
        }

        // ---- alpha from fragments: quad-reduce over tig ----
        {
            float sa[2] = {0.f, 0.f};
            float sd[2] = {0.f, 0.f};
#pragma unroll
            for (int nt = 0; nt < 4; nt++) {
                float2 av = __ldg((const float2*)&asrc[head * 32 + nt * 8 + 2 * tig]);
                float2 dv = __ldg((const float2*)&adst[head * 32 + nt * 8 + 2 * tig]);
                sa[0] += C[nt][0] * av.x + C[nt][1] * av.y;
                sa[1] += C[nt][2] * av.x + C[nt][3] * av.y;
                sd[0] += C[nt][0] * dv.x + C[nt][1] * dv.y;
                sd[1] += C[nt][2] * dv.x + C[nt][3] * dv.y;
            }
#pragma unroll
            for (int tm = 0; tm < 2; tm++) {
                sa[tm] += __shfl_xor_sync(0xffffffffu, sa[tm], 1);
                sa[tm] += __shfl_xor_sync(0xffffffffu, sa[tm], 2);
                sd[tm] += __shfl_xor_sync(0xffffffffu, sd[tm], 1);
                sd[tm] += __shfl_xor_sync(0xffffffffu, sd[tm], 2);
                const int token = mt * 16 + tm * 8 + g;
                as_sh[head * 32 + token] = sa[tm];
                ad_sh[head * 32 + token] = sd[tm];
            }
        }

        // all same-mt warps must finish reading xs rows before h overwrites them;
        // also publishes as_sh/ad_sh for the whole head.
        __syncthreads();

        // ---- store h (own 16 rows) into this head's xs band ----
#pragma unroll
        for (int nt = 0; nt < 4; nt++) {
            float* hp = &xs[(mt * 16 + g) * XSROW + head * 32 + nt * 8 + 2 * tig];
            *(float2*)hp               = make_float2(C[nt][0], C[nt][1]);
            *(float2*)(hp + 8 * XSROW) = make_float2(C[nt][2], C[nt][3]);
        }

        // ---- softmax p (unnormalized) for own 16 queries : lanes 0-15 ----
        if (lane < 16) {
            const int i = mt * 16 + lane;
            const float a_i = as_sh[head * 32 + i];
            float p[32];
            float m = -1e30f;
#pragma unroll
            for (int j = 0; j < 32; j++) {
                float e = a_i + ad_sh[head * 32 + j];
                e = fmaxf(e, 0.2f * e);                 // leaky relu
                p[j] = (alive[j] > 0.5f) ? e : -1e30f;  // mask
                m = fmaxf(m, p[j]);
            }
            float s = 0.f;
#pragma unroll
            for (int j = 0; j < 32; j++) { p[j] = __expf(p[j] - m); s += p[j]; }
            inv_sh[head * 32 + i] = 1.0f / s;
            float* pr = &pbuf[head][i][0];
#pragma unroll
            for (int q = 0; q < 8; q++)
                *(float4*)&pr[q * 4] = make_float4(p[q*4], p[q*4+1], p[q*4+2], p[q*4+3]);
        }

        pair_bar(head);   // both halves: h rows 0..31 + p complete for this head

        // ---- aggregation: out[mt half] = (p @ h) * inv, ELU; tf32 mma 2-term ----
        {
            float Dg[4][4];
#pragma unroll
            for (int nt = 0; nt < 4; nt++)
#pragma unroll
                for (int r = 0; r < 4; r++) Dg[nt][r] = 0.f;

#pragma unroll
            for (int kb = 0; kb < 4; kb++) {
                const float* pp = &pbuf[head][mt * 16 + g][kb * 8 + tig];
                unsigned pa0 = hi_tf32(pp[0]);
                unsigned pa1 = hi_tf32(pp[8 * PST]);
                unsigned pa2 = hi_tf32(pp[4]);
                unsigned pa3 = hi_tf32(pp[8 * PST + 4]);
#pragma unroll
                for (int nt = 0; nt < 4; nt++) {
                    const int col = head * 32 + nt * 8 + g;
                    float b0f = xs[(kb * 8 + tig) * XSROW + col];
                    float b1f = xs[(kb * 8 + tig + 4) * XSROW + col];
                    unsigned bh0, bl0, bh1, bl1;
                    split_tf32(b0f, bh0, bl0);
                    split_tf32(b1f, bh1, bl1);
                    mma_tf32(Dg[nt], pa0, pa1, pa2, pa3, bh0, bh1);
                    mma_tf32(Dg[nt], pa0, pa1, pa2, pa3, bl0, bl1);
                }
            }

            pair_bar(head);   // both halves done reading h before overwrite

            const float inv0 = inv_sh[head * 32 + mt * 16 + g];
            const float inv1 = inv_sh[head * 32 + mt * 16 + g + 8];
#pragma unroll
            for (int nt = 0; nt < 4; nt++) {
                float* op = &xs[(mt * 16 + g) * XSROW + head * 32 + nt * 8 + 2 * tig];
                float o0 = elu1(Dg[nt][0] * inv0);
                float o1 = elu1(Dg[nt][1] * inv0);
                float o2 = elu1(Dg[nt][2] * inv1);
                float o3 = elu1(Dg[nt][3] * inv1);
                *(float2*)op               = make_float2(o0, o1);
                *(float2*)(op + 8 * XSROW) = make_float2(o2, o3);
            }
        }
        __syncthreads();   // all head bands rewritten before next GEMM / pool
    }

    // ---- masked mean pool: threads 0-127 = output features ----
    if (tid < 128) {
        float s = 0.f;
#pragma unroll
        for (int i = 0; i < 32; i++)
            s += alive[i] * xs[i * XSROW + tid];
        out[(long)b * 128 + tid] = s * inv_cnt_sh;
    }
}

extern "C" void kernel_launch(void* const* d_in, const int* in_sizes, int n_in,
                              void* d_out, int out_size)
{
    const float* gobs = (const float*)d_in[0];
    const float* Wv   = (const float*)d_in[1];
    const float* bv   = (const float*)d_in[2];
    const float* Wp   = (const float*)d_in[3];
    const float* bp   = (const float*)d_in[4];
    const float* w0   = (const float*)d_in[5];
    const float* as0  = (const float*)d_in[6];
    const float* ad0  = (const float*)d_in[7];
    const float* w1   = (const float*)d_in[8];
    const float* as1  = (const float*)d_in[9];
    const float* ad1  = (const float*)d_in[10];

    const int B = in_sizes[0] / 1056;

    gnn_critic_kernel<<<B, 256>>>(gobs, Wv, bv, Wp, bp,
                                  w0, as0, ad0, w1, as1, ad1,
                                  (float*)d_out);
}

// round 16
// speedup vs baseline: 1.2276x; 1.2276x over previous
#include <cuda_runtime.h>
#include <cstdint>

// GNN critic encoder, fully fused: one CTA per batch row.
// R15 = R11 structure (warp = head, tf32 mma GEMM 3-term + aggregation 2-term,
//       h aliased into xs band) with the cp.async weight ring removed:
//       B fragments stream directly from L2 via __ldg, smem ~37KB -> 6 CTAs/SM.

#define XSROW 132      // xs token-row stride: 132 % 32 == 4 -> frag reads conflict-free
#define PST   36       // pbuf row stride: 4*i+j banks -> A-frag reads conflict-free

__device__ __forceinline__ float elu1(float v) { return v > 0.f ? v : expm1f(v); }

// tf32 split: hi = top 10 mantissa bits (valid tf32), lo = exact residual
__device__ __forceinline__ void split_tf32(float v, unsigned& hi, unsigned& lo) {
    unsigned u = __float_as_uint(v) & 0xFFFFE000u;
    hi = u;
    lo = __float_as_uint(v - __uint_as_float(u));
}
__device__ __forceinline__ unsigned hi_tf32(float v) {
    return __float_as_uint(v) & 0xFFFFE000u;
}

__device__ __forceinline__ void mma_tf32(float c[4],
                                         unsigned a0, unsigned a1, unsigned a2, unsigned a3,
                                         unsigned b0, unsigned b1) {
    asm volatile(
        "mma.sync.aligned.m16n8k8.row.col.f32.tf32.tf32.f32 "
        "{%0,%1,%2,%3}, {%4,%5,%6,%7}, {%8,%9}, {%0,%1,%2,%3};"
        : "+f"(c[0]), "+f"(c[1]), "+f"(c[2]), "+f"(c[3])
        : "r"(a0), "r"(a1), "r"(a2), "r"(a3), "r"(b0), "r"(b1));
}

// Token embedding -> xs (token-major [32][XSROW]). Cols: lane, lane+32, lane+64, lane+96.
template<int D>
__device__ __forceinline__ void embed_tokens(const float* __restrict__ obs_tok,
                                             const float* __restrict__ W,
                                             const float* __restrict__ bias,
                                             float* __restrict__ xs,
                                             int t0, int lane)
{
    float bb[4];
#pragma unroll
    for (int c = 0; c < 4; c++) bb[c] = __ldg(&bias[lane + 32 * c]);
    float acc[8][4];
#pragma unroll
    for (int r = 0; r < 8; r++)
#pragma unroll
        for (int c = 0; c < 4; c++) acc[r][c] = bb[c];
#pragma unroll 4
    for (int d = 0; d < D; d++) {
        float wv[4];
#pragma unroll
        for (int c = 0; c < 4; c++) wv[c] = __ldg(&W[d * 128 + lane + 32 * c]);
#pragma unroll
        for (int r = 0; r < 8; r++) {
            float xv = obs_tok[r * D + d];
#pragma unroll
            for (int c = 0; c < 4; c++) acc[r][c] += xv * wv[c];
        }
    }
#pragma unroll
    for (int r = 0; r < 8; r++)
#pragma unroll
        for (int c = 0; c < 4; c++)
            xs[(t0 + r) * XSROW + lane + 32 * c] = acc[r][c];
}

__global__ __launch_bounds__(128, 6)
void gnn_critic_kernel(const float* __restrict__ gobs,
                       const float* __restrict__ Wv, const float* __restrict__ bv,
                       const float* __restrict__ Wp, const float* __restrict__ bp,
                       const float* __restrict__ w0g, const float* __restrict__ as0,
                       const float* __restrict__ ad0,
                       const float* __restrict__ w1g, const float* __restrict__ as1,
                       const float* __restrict__ ad1,
                       float* __restrict__ out)
{
    __shared__ float xs[32 * XSROW];                  // activations / h (head bands alias)
    __shared__ __align__(16) float pbuf[4][32][PST];  // per-head unnormalized attn p
    __shared__ float as_sh[128];                      // [head*32 + token]
    __shared__ float ad_sh[128];
    __shared__ float inv_sh[128];                     // per (head, query) 1/sum
    __shared__ float alive[32];
    __shared__ float inv_cnt_sh;

    float* obs = &pbuf[0][0][0];                      // 1056 <= 4608; dead before softmax L0

    const int tid  = threadIdx.x;
    const int lane = tid & 31;
    const int warp = tid >> 5;                        // == head
    const int b    = blockIdx.x;
    const int g    = lane >> 2;                       // mma group (row in tile)
    const int tig  = lane & 3;                        // thread-in-group

    // ---- load obs row ----
    const float* rowp = gobs + (long)b * 1056;
    for (int i = tid; i < 1056; i += 128) obs[i] = __ldg(&rowp[i]);
    __syncthreads();

    // ---- alive mask + all-dead fix + pool count ----
    if (warp == 0) {
        float v = (obs[1024 + lane] >= 0.5f) ? 1.0f : 0.0f;
        float s = v;
#pragma unroll
        for (int o = 16; o; o >>= 1) s += __shfl_xor_sync(0xffffffffu, s, o);
        float vv = (s < 0.5f) ? 1.0f : v;
        alive[lane] = vv;
        if (lane == 0) {
            float cnt = (s < 0.5f) ? 32.0f : s;
            inv_cnt_sh = 1.0f / fmaxf(cnt, 1.0f);
        }
    }
    __syncthreads();

    // ---- token embedding ----
    if (warp < 2)
        embed_tokens<40>(obs + warp * 8 * 40, Wv, bv, xs, warp * 8, lane);
    else
        embed_tokens<24>(obs + 640 + (warp - 2) * 8 * 24, Wp, bp, xs, (warp - 2) * 8 + 16, lane);
    __syncthreads();          // xs + alive ready; obs (pbuf) dead

    for (int L = 0; L < 2; L++) {
        const float* w    = (L ? w1g : w0g) + warp * 32;     // this head's column band
        const float* asrc = L ? as1 : as0;
        const float* adst = L ? ad1 : ad0;

        // ---- GEMM: h = x @ w via tf32 mma, 3-term compensated. warp = head. ----
        float C[2][4][4];                    // [mtile][ntile][frag]
#pragma unroll
        for (int mt = 0; mt < 2; mt++)
#pragma unroll
            for (int nt = 0; nt < 4; nt++)
#pragma unroll
                for (int r = 0; r < 4; r++) C[mt][nt][r] = 0.f;

#pragma unroll 2
        for (int kb = 0; kb < 16; kb++) {
            // B fragments straight from global (weights are L2-resident):
            // batch all 8 loads first for MLP.
            const float* wk = w + (kb * 8 + tig) * 128;
            float bf[4][2];
#pragma unroll
            for (int nt = 0; nt < 4; nt++) {
                bf[nt][0] = __ldg(&wk[nt * 8 + g]);
                bf[nt][1] = __ldg(&wk[4 * 128 + nt * 8 + g]);
            }
            // A fragments, split hi/lo
            unsigned ah[2][4], al[2][4];
#pragma unroll
            for (int mt = 0; mt < 2; mt++) {
                const int r0 = (mt * 16 + g) * XSROW + kb * 8 + tig;
                split_tf32(xs[r0],                 ah[mt][0], al[mt][0]);
                split_tf32(xs[r0 + 8 * XSROW],     ah[mt][1], al[mt][1]);
                split_tf32(xs[r0 + 4],             ah[mt][2], al[mt][2]);
                split_tf32(xs[r0 + 8 * XSROW + 4], ah[mt][3], al[mt][3]);
            }
#pragma unroll
            for (int nt = 0; nt < 4; nt++) {
                unsigned bh0, bl0, bh1, bl1;
                split_tf32(bf[nt][0], bh0, bl0);
                split_tf32(bf[nt][1], bh1, bl1);
#pragma unroll
                for (int mt = 0; mt < 2; mt++) {
                    mma_tf32(C[mt][nt], ah[mt][0], ah[mt][1], ah[mt][2], ah[mt][3], bh0, bh1);
                    mma_tf32(C[mt][nt], ah[mt][0], ah[mt][1], ah[mt][2], ah[mt][3], bl0, bl1);
                    mma_tf32(C[mt][nt], al[mt][0], al[mt][1], al[mt][2], al[mt][3], bh0, bh1);
                }
            }
        }

        // ---- alpha from fragments: quad-reduce over tig ----
        {
            float sa[4] = {0.f, 0.f, 0.f, 0.f};
            float sd[4] = {0.f, 0.f, 0.f, 0.f};
#pragma unroll
            for (int nt = 0; nt < 4; nt++) {
                float2 av = __ldg((const float2*)&asrc[warp * 32 + nt * 8 + 2 * tig]);
                float2 dv = __ldg((const float2*)&adst[warp * 32 + nt * 8 + 2 * tig]);
#pragma unroll
                for (int mt = 0; mt < 2; mt++) {
                    sa[mt*2+0] += C[mt][nt][0] * av.x + C[mt][nt][1] * av.y;
                    sa[mt*2+1] += C[mt][nt][2] * av.x + C[mt][nt][3] * av.y;
                    sd[mt*2+0] += C[mt][nt][0] * dv.x + C[mt][nt][1] * dv.y;
                    sd[mt*2+1] += C[mt][nt][2] * dv.x + C[mt][nt][3] * dv.y;
                }
            }
#pragma unroll
            for (int tm = 0; tm < 4; tm++) {
                sa[tm] += __shfl_xor_sync(0xffffffffu, sa[tm], 1);
                sa[tm] += __shfl_xor_sync(0xffffffffu, sa[tm], 2);
                sd[tm] += __shfl_xor_sync(0xffffffffu, sd[tm], 1);
                sd[tm] += __shfl_xor_sync(0xffffffffu, sd[tm], 2);
                const int token = (tm >> 1) * 16 + (tm & 1) * 8 + g;
                as_sh[warp * 32 + token] = sa[tm];
                ad_sh[warp * 32 + token] = sd[tm];
            }
        }

        // ---- release xs (all warps finished GEMM reads), then store h into xs band ----
        __syncthreads();
#pragma unroll
        for (int mt = 0; mt < 2; mt++)
#pragma unroll
            for (int nt = 0; nt < 4; nt++) {
                float* hp = &xs[(mt * 16 + g) * XSROW + warp * 32 + nt * 8 + 2 * tig];
                *(float2*)hp               = make_float2(C[mt][nt][0], C[mt][nt][1]);
                *(float2*)(hp + 8 * XSROW) = make_float2(C[mt][nt][2], C[mt][nt][3]);
            }
        __syncwarp();

        // ---- softmax weights p (unnormalized) : lane = query i ----
        {
            const int i = lane;
            const float a_i = as_sh[warp * 32 + i];
            float p[32];
            float m = -1e30f;
#pragma unroll
            for (int j = 0; j < 32; j++) {
                float e = a_i + ad_sh[warp * 32 + j];
                e = fmaxf(e, 0.2f * e);                 // leaky relu
                p[j] = (alive[j] > 0.5f) ? e : -1e30f;  // mask
                m = fmaxf(m, p[j]);
            }
            float s = 0.f;
#pragma unroll
            for (int j = 0; j < 32; j++) { p[j] = __expf(p[j] - m); s += p[j]; }
            inv_sh[warp * 32 + i] = 1.0f / s;
            float* pr = &pbuf[warp][i][0];
#pragma unroll
            for (int q = 0; q < 8; q++)
                *(float4*)&pr[q * 4] = make_float4(p[q*4], p[q*4+1], p[q*4+2], p[q*4+3]);
        }
        __syncwarp();

        // ---- aggregation: out = (p @ h) * inv, ELU; tf32 mma 2-term ----
        {
            float Dg[2][4][4];
#pragma unroll
            for (int mt = 0; mt < 2; mt++)
#pragma unroll
                for (int nt = 0; nt < 4; nt++)
#pragma unroll
                    for (int r = 0; r < 4; r++) Dg[mt][nt][r] = 0.f;

#pragma unroll
            for (int kb = 0; kb < 4; kb++) {
                unsigned pa[2][4];
#pragma unroll
                for (int mt = 0; mt < 2; mt++) {
                    const float* pp = &pbuf[warp][mt * 16 + g][kb * 8 + tig];
                    pa[mt][0] = hi_tf32(pp[0]);
                    pa[mt][1] = hi_tf32(pp[8 * PST]);
                    pa[mt][2] = hi_tf32(pp[4]);
                    pa[mt][3] = hi_tf32(pp[8 * PST + 4]);
                }
#pragma unroll
                for (int nt = 0; nt < 4; nt++) {
                    const int col = warp * 32 + nt * 8 + g;
                    float b0f = xs[(kb * 8 + tig) * XSROW + col];
                    float b1f = xs[(kb * 8 + tig + 4) * XSROW + col];
                    unsigned bh0, bl0, bh1, bl1;
                    split_tf32(b0f, bh0, bl0);
                    split_tf32(b1f, bh1, bl1);
#pragma unroll
                    for (int mt = 0; mt < 2; mt++) {
                        mma_tf32(Dg[mt][nt], pa[mt][0], pa[mt][1], pa[mt][2], pa[mt][3], bh0, bh1);
                        mma_tf32(Dg[mt][nt], pa[mt][0], pa[mt][1], pa[mt][2], pa[mt][3], bl0, bl1);
                    }
                }
            }
            // normalize per query row, ELU, store back into the same xs band
            __syncwarp();   // all h reads done before overwriting
#pragma unroll
            for (int mt = 0; mt < 2; mt++) {
                const float inv0 = inv_sh[warp * 32 + mt * 16 + g];
                const float inv1 = inv_sh[warp * 32 + mt * 16 + g + 8];
#pragma unroll
                for (int nt = 0; nt < 4; nt++) {
                    float* op = &xs[(mt * 16 + g) * XSROW + warp * 32 + nt * 8 + 2 * tig];
                    float o0 = elu1(Dg[mt][nt][0] * inv0);
                    float o1 = elu1(Dg[mt][nt][1] * inv0);
                    float o2 = elu1(Dg[mt][nt][2] * inv1);
                    float o3 = elu1(Dg[mt][nt][3] * inv1);
                    *(float2*)op               = make_float2(o0, o1);
                    *(float2*)(op + 8 * XSROW) = make_float2(o2, o3);
                }
            }
        }
        __syncthreads();   // all head bands rewritten before next GEMM / pool
    }

    // ---- masked mean pool: thread = output feature ----
    {
        float s = 0.f;
#pragma unroll
        for (int i = 0; i < 32; i++)
            s += alive[i] * xs[i * XSROW + tid];
        out[(long)b * 128 + tid] = s * inv_cnt_sh;
    }
}

extern "C" void kernel_launch(void* const* d_in, const int* in_sizes, int n_in,
                              void* d_out, int out_size)
{
    const float* gobs = (const float*)d_in[0];
    const float* Wv   = (const float*)d_in[1];
    const float* bv   = (const float*)d_in[2];
    const float* Wp   = (const float*)d_in[3];
    const float* bp   = (const float*)d_in[4];
    const float* w0   = (const float*)d_in[5];
    const float* as0  = (const float*)d_in[6];
    const float* ad0  = (const float*)d_in[7];
    const float* w1   = (const float*)d_in[8];
    const float* as1  = (const float*)d_in[9];
    const float* ad1  = (const float*)d_in[10];

    const int B = in_sizes[0] / 1056;

    gnn_critic_kernel<<<B, 128>>>(gobs, Wv, bv, Wp, bp,
                                  w0, as0, ad0, w1, as1, ad1,
                                  (float*)d_out);
}